// round 2
// baseline (speedup 1.0000x reference)
#include <cuda_runtime.h>
#include <cuda_bf16.h>
#include <math.h>
#include <float.h>

#define WAY 5
#define SHOT 5
#define QUERY 15
#define EMB 640
#define NMEM 100000
#define NSIM (SHOT + NMEM)   // 100005 candidates per way
#define TOPK 8
#define EPS 1e-12f
#define INV_TEMP (1.0f / 64.0f)

#define ROWS_PER_WARP 8

// ---------------- device scratch (static, allocation-free) ----------------
__device__ float g_c[WAY][EMB];          // per-way centroid of normalized supports
__device__ float g_supn[SHOT * WAY][EMB];// normalized support rows (row r = inst row r)
__device__ float g_sim[WAY][NSIM];       // full similarity vector per way
__device__ float g_topv[WAY][TOPK];
__device__ int   g_topi[WAY][TOPK];
__device__ float g_proto[WAY][EMB];      // normalized prototypes

// ---------------- kernel 1: supports -> sup_n, centroids, sim_sup ----------
// one block, 800 threads = 25 warps (warp per support row)
__global__ void k1_support(const float* __restrict__ inst) {
    int wid  = threadIdx.x >> 5;
    int lane = threadIdx.x & 31;

    if (wid < SHOT * WAY) {
        const float* row = inst + wid * EMB;
        float v[20];
        float ss = 0.f;
#pragma unroll
        for (int i = 0; i < 20; i++) {
            v[i] = row[lane + 32 * i];
            ss += v[i] * v[i];
        }
#pragma unroll
        for (int o = 16; o; o >>= 1) ss += __shfl_xor_sync(0xffffffffu, ss, o);
        float inv = 1.0f / fmaxf(sqrtf(ss), EPS);
#pragma unroll
        for (int i = 0; i < 20; i++) g_supn[wid][lane + 32 * i] = v[i] * inv;
    }
    __syncthreads();

    // centroids c[w][d] = mean over s of g_supn[s*WAY + w][d]
    for (int idx = threadIdx.x; idx < WAY * EMB; idx += blockDim.x) {
        int w = idx / EMB, d = idx % EMB;
        float s = 0.f;
#pragma unroll
        for (int t = 0; t < SHOT; t++) s += g_supn[t * WAY + w][d];
        g_c[w][d] = s * (1.0f / SHOT);
    }
    __syncthreads();

    // sim_sup[w][t] = <c[w], sup_n[w,t]>   (warp per (w,t) pair)
    if (wid < WAY * SHOT) {
        int w = wid / SHOT, t = wid % SHOT;
        float dot = 0.f;
        for (int i = lane; i < EMB; i += 32)
            dot += g_c[w][i] * g_supn[t * WAY + w][i];
#pragma unroll
        for (int o = 16; o; o >>= 1) dot += __shfl_xor_sync(0xffffffffu, dot, o);
        if (lane == 0) g_sim[w][t] = dot;
    }
}

// ---------------- kernel 2: memory-bank scan (dominant, HBM-bound) ---------
// each warp handles ROWS_PER_WARP consecutive rows; centroid float4s are
// loaded once per i-chunk and reused across the 8 rows (8x LDS amortization).
__global__ void __launch_bounds__(256) k2_memscan(const float* __restrict__ mem) {
    __shared__ float sc[WAY][EMB];   // 12.8 KB
    for (int i = threadIdx.x; i < WAY * EMB; i += blockDim.x)
        ((float*)sc)[i] = ((const float*)g_c)[i];
    __syncthreads();

    int wg   = (blockIdx.x * blockDim.x + threadIdx.x) >> 5;
    int lane = threadIdx.x & 31;
    int row0 = wg * ROWS_PER_WARP;
    if (row0 >= NMEM) return;

    float acc0[ROWS_PER_WARP], acc1[ROWS_PER_WARP], acc2[ROWS_PER_WARP];
    float acc3[ROWS_PER_WARP], acc4[ROWS_PER_WARP], ssq[ROWS_PER_WARP];
#pragma unroll
    for (int r = 0; r < ROWS_PER_WARP; r++) {
        acc0[r] = acc1[r] = acc2[r] = acc3[r] = acc4[r] = ssq[r] = 0.f;
    }

#pragma unroll
    for (int i = 0; i < 5; i++) {
        int dbase = 4 * (lane + 32 * i);
        float4 c0 = *(const float4*)&sc[0][dbase];
        float4 c1 = *(const float4*)&sc[1][dbase];
        float4 c2 = *(const float4*)&sc[2][dbase];
        float4 c3 = *(const float4*)&sc[3][dbase];
        float4 c4 = *(const float4*)&sc[4][dbase];
#pragma unroll
        for (int r = 0; r < ROWS_PER_WARP; r++) {
            const float4* rp = (const float4*)(mem + (size_t)(row0 + r) * EMB);
            float4 v = __ldg(&rp[lane + 32 * i]);
            ssq[r]  += v.x * v.x  + v.y * v.y  + v.z * v.z  + v.w * v.w;
            acc0[r] += v.x * c0.x + v.y * c0.y + v.z * c0.z + v.w * c0.w;
            acc1[r] += v.x * c1.x + v.y * c1.y + v.z * c1.z + v.w * c1.w;
            acc2[r] += v.x * c2.x + v.y * c2.y + v.z * c2.z + v.w * c2.w;
            acc3[r] += v.x * c3.x + v.y * c3.y + v.z * c3.z + v.w * c3.w;
            acc4[r] += v.x * c4.x + v.y * c4.y + v.z * c4.z + v.w * c4.w;
        }
    }

#pragma unroll
    for (int r = 0; r < ROWS_PER_WARP; r++) {
#pragma unroll
        for (int o = 16; o; o >>= 1) {
            ssq[r]  += __shfl_xor_sync(0xffffffffu, ssq[r],  o);
            acc0[r] += __shfl_xor_sync(0xffffffffu, acc0[r], o);
            acc1[r] += __shfl_xor_sync(0xffffffffu, acc1[r], o);
            acc2[r] += __shfl_xor_sync(0xffffffffu, acc2[r], o);
            acc3[r] += __shfl_xor_sync(0xffffffffu, acc3[r], o);
            acc4[r] += __shfl_xor_sync(0xffffffffu, acc4[r], o);
        }
        float inv = 1.0f / fmaxf(sqrtf(ssq[r]), EPS);
        if (lane < WAY) {
            float a = (lane == 0) ? acc0[r] :
                      (lane == 1) ? acc1[r] :
                      (lane == 2) ? acc2[r] :
                      (lane == 3) ? acc3[r] : acc4[r];
            g_sim[lane][SHOT + row0 + r] = a * inv;
        }
    }
}

// ---------------- kernel 3: top-8 per way ----------------------------------
#define K3_THREADS 512
__device__ __forceinline__ void merge8(float* av, int* ai,
                                       const float* bv, const int* bi) {
    float tv[TOPK]; int ti[TOPK];
    int ia = 0, ib = 0;
#pragma unroll
    for (int k = 0; k < TOPK; k++) {
        float va = av[ia], vb = bv[ib];
        bool takeA = (va > vb) || (va == vb && ai[ia] <= bi[ib]);
        if (takeA) { tv[k] = va; ti[k] = ai[ia]; ia++; }
        else       { tv[k] = vb; ti[k] = bi[ib]; ib++; }
    }
#pragma unroll
    for (int k = 0; k < TOPK; k++) { av[k] = tv[k]; ai[k] = ti[k]; }
}

__global__ void k3_topk() {
    int w = blockIdx.x;
    const float* sim = g_sim[w];

    float bv[TOPK]; int bi[TOPK];
#pragma unroll
    for (int j = 0; j < TOPK; j++) { bv[j] = -FLT_MAX; bi[j] = 0x7fffffff; }

    for (int i = threadIdx.x; i < NSIM; i += K3_THREADS) {
        float v = sim[i];
        if (v > bv[TOPK - 1]) {
            int j = TOPK - 1;
            while (j > 0 && v > bv[j - 1]) { bv[j] = bv[j - 1]; bi[j] = bi[j - 1]; j--; }
            bv[j] = v; bi[j] = i;
        }
    }

    __shared__ float shv[K3_THREADS][TOPK];
    __shared__ int   shi[K3_THREADS][TOPK];
#pragma unroll
    for (int j = 0; j < TOPK; j++) { shv[threadIdx.x][j] = bv[j]; shi[threadIdx.x][j] = bi[j]; }
    __syncthreads();

    for (int s = K3_THREADS / 2; s >= 1; s >>= 1) {
        if (threadIdx.x < s)
            merge8(shv[threadIdx.x], shi[threadIdx.x],
                   shv[threadIdx.x + s], shi[threadIdx.x + s]);
        __syncthreads();
    }
    if (threadIdx.x < TOPK) {
        g_topv[w][threadIdx.x] = shv[0][threadIdx.x];
        g_topi[w][threadIdx.x] = shi[0][threadIdx.x];
    }
}

// ---------------- kernel 4: prototype build + normalize --------------------
// block per way, 640 threads (one per dim)
__global__ void k4_proto(const float* __restrict__ inst,
                         const float* __restrict__ mem) {
    int w = blockIdx.x;
    int tid = threadIdx.x;

    __shared__ float svals[TOPK];
    __shared__ int   sidx[TOPK];
    __shared__ float red[32];
    if (tid < TOPK) { svals[tid] = g_topv[w][tid]; sidx[tid] = g_topi[w][tid]; }
    __syncthreads();

    float denom = 0.f;
#pragma unroll
    for (int j = 0; j < TOPK; j++) denom += svals[j];

    float numer = 0.f;
#pragma unroll
    for (int j = 0; j < TOPK; j++) {
        int idx = sidx[j];
        const float* src = (idx < SHOT)
            ? inst + (size_t)(idx * WAY + w) * EMB
            : mem + (size_t)(idx - SHOT) * EMB;
        numer += svals[j] * src[tid];
    }
    float p = numer / denom;

    // block reduce sum of squares over 640 threads (20 warps)
    float ss = p * p;
    int lane = tid & 31, wid = tid >> 5;
#pragma unroll
    for (int o = 16; o; o >>= 1) ss += __shfl_xor_sync(0xffffffffu, ss, o);
    if (lane == 0) red[wid] = ss;
    __syncthreads();
    if (wid == 0) {
        float t = (lane < (blockDim.x >> 5)) ? red[lane] : 0.f;
#pragma unroll
        for (int o = 16; o; o >>= 1) t += __shfl_xor_sync(0xffffffffu, t, o);
        if (lane == 0) red[0] = 1.0f / fmaxf(sqrtf(t), EPS);
    }
    __syncthreads();
    g_proto[w][tid] = p * red[0];
}

// ---------------- kernel 5: logits ----------------------------------------
// block per query (75 blocks), 160 threads = 5 warps (warp per way)
__global__ void k5_logits(const float* __restrict__ inst, float* __restrict__ out) {
    int q = blockIdx.x;
    int w = threadIdx.x >> 5;
    int lane = threadIdx.x & 31;
    const float* qr = inst + (size_t)(SHOT * WAY + q) * EMB;

    float dot = 0.f;
#pragma unroll
    for (int i = 0; i < 20; i++) {
        int d = lane + 32 * i;
        dot += qr[d] * g_proto[w][d];
    }
#pragma unroll
    for (int o = 16; o; o >>= 1) dot += __shfl_xor_sync(0xffffffffu, dot, o);
    if (lane == 0) out[q * WAY + w] = dot * INV_TEMP;
}

// ---------------- launch ----------------------------------------------------
extern "C" void kernel_launch(void* const* d_in, const int* in_sizes, int n_in,
                              void* d_out, int out_size) {
    const float* inst = (const float*)d_in[0];   // [100, 640] fp32
    const float* mem  = (const float*)d_in[1];   // [100000, 640] fp32
    float* out = (float*)d_out;                  // [75, 5] fp32

    k1_support<<<1, 800>>>(inst);

    int warps = (NMEM + ROWS_PER_WARP - 1) / ROWS_PER_WARP;   // 12500
    int blocks = (warps + 7) / 8;                              // 1563
    k2_memscan<<<blocks, 256>>>(mem);

    k3_topk<<<WAY, K3_THREADS>>>();
    k4_proto<<<WAY, EMB>>>(inst, mem);
    k5_logits<<<QUERY * WAY, WAY * 32>>>(inst, out);
}

// round 3
// speedup vs baseline: 1.1839x; 1.1839x over previous
#include <cuda_runtime.h>
#include <cuda_bf16.h>
#include <math.h>
#include <float.h>

#define WAY 5
#define SHOT 5
#define QUERY 15
#define EMB 640
#define NMEM 100000
#define NSIM (SHOT + NMEM)   // 100005 candidates per way
#define TOPK 8
#define EPS 1e-12f
#define INV_TEMP (1.0f / 64.0f)

#define ROWS 4               // rows per warp in k2

typedef unsigned long long ull;

// ---------------- device scratch (static, allocation-free) ----------------
__device__ float g_c[WAY][EMB];           // per-way centroid of normalized supports
__device__ float g_supn[SHOT * WAY][EMB]; // normalized support rows
__device__ float g_sim[WAY][NSIM];        // similarity vector per way
__device__ float g_proto[WAY][EMB];       // normalized prototypes

// ---------------- packed f32x2 helpers -------------------------------------
__device__ __forceinline__ void ffma2(ull& d, ull a, ull b) {
    asm("fma.rn.f32x2 %0, %1, %2, %0;" : "+l"(d) : "l"(a), "l"(b));
}
__device__ __forceinline__ float2 upk(ull v) {
    float2 f;
    asm("mov.b64 {%0,%1}, %2;" : "=f"(f.x), "=f"(f.y) : "l"(v));
    return f;
}
__device__ __forceinline__ void ldg_cs128(ull& a, ull& b, const ull* p) {
    asm("ld.global.cs.v2.u64 {%0,%1}, [%2];" : "=l"(a), "=l"(b) : "l"(p));
}

// ---------------- kernel 1: supports -> sup_n, centroids, sim_sup ----------
__global__ void k1_support(const float* __restrict__ inst) {
    int wid  = threadIdx.x >> 5;
    int lane = threadIdx.x & 31;

    if (wid < SHOT * WAY) {
        const float* row = inst + wid * EMB;
        float v[20];
        float ss = 0.f;
#pragma unroll
        for (int i = 0; i < 20; i++) {
            v[i] = row[lane + 32 * i];
            ss += v[i] * v[i];
        }
#pragma unroll
        for (int o = 16; o; o >>= 1) ss += __shfl_xor_sync(0xffffffffu, ss, o);
        float inv = 1.0f / fmaxf(sqrtf(ss), EPS);
#pragma unroll
        for (int i = 0; i < 20; i++) g_supn[wid][lane + 32 * i] = v[i] * inv;
    }
    __syncthreads();

    for (int idx = threadIdx.x; idx < WAY * EMB; idx += blockDim.x) {
        int w = idx / EMB, d = idx % EMB;
        float s = 0.f;
#pragma unroll
        for (int t = 0; t < SHOT; t++) s += g_supn[t * WAY + w][d];
        g_c[w][d] = s * (1.0f / SHOT);
    }
    __syncthreads();

    if (wid < WAY * SHOT) {
        int w = wid / SHOT, t = wid % SHOT;
        float dot = 0.f;
        for (int i = lane; i < EMB; i += 32)
            dot += g_c[w][i] * g_supn[t * WAY + w][i];
#pragma unroll
        for (int o = 16; o; o >>= 1) dot += __shfl_xor_sync(0xffffffffu, dot, o);
        if (lane == 0) g_sim[w][t] = dot;
    }
}

// ---------------- kernel 2: memory-bank scan (HBM-bound target) ------------
// warp handles 4 rows; f32x2 FMAs; explicit double-buffered loads for MLP>=4.
__global__ void __launch_bounds__(256, 2) k2_memscan(const float* __restrict__ mem) {
    __shared__ ull sc[WAY][EMB / 2];   // centroids as packed f32x2, 12.8 KB
    {
        const ull* gc = (const ull*)g_c;
        ull* s = &sc[0][0];
        for (int i = threadIdx.x; i < WAY * EMB / 2; i += blockDim.x) s[i] = gc[i];
    }
    __syncthreads();

    int wg   = (blockIdx.x * blockDim.x + threadIdx.x) >> 5;
    int lane = threadIdx.x & 31;
    int row0 = wg * ROWS;
    if (row0 >= NMEM) return;

    // row base pointers in 16B units (one ulonglong2 = one float4); row stride = 160
    const ull* base = (const ull*)(mem + (size_t)row0 * EMB);

    ull acc[ROWS][6];
#pragma unroll
    for (int r = 0; r < ROWS; r++)
#pragma unroll
        for (int k = 0; k < 6; k++) acc[r][k] = 0ull;

    // prefetch chunk 0: each chunk covers float4 index lane + 32*i
    ull vx[ROWS], vy[ROWS];
#pragma unroll
    for (int r = 0; r < ROWS; r++)
        ldg_cs128(vx[r], vy[r], base + (size_t)r * 320 + 2 * lane);

#pragma unroll
    for (int i = 0; i < 5; i++) {
        // centroid chunk from shared (packed f32x2)
        ull cw[WAY][2];
#pragma unroll
        for (int w = 0; w < WAY; w++) {
            cw[w][0] = sc[w][2 * (lane + 32 * i)];
            cw[w][1] = sc[w][2 * (lane + 32 * i) + 1];
        }
        // prefetch next chunk (batched: all LDGs issued before FMAs)
        ull nx[ROWS], ny[ROWS];
        if (i < 4) {
#pragma unroll
            for (int r = 0; r < ROWS; r++)
                ldg_cs128(nx[r], ny[r], base + (size_t)r * 320 + 2 * (lane + 32 * (i + 1)));
        }
#pragma unroll
        for (int r = 0; r < ROWS; r++) {
            ffma2(acc[r][5], vx[r], vx[r]);
            ffma2(acc[r][5], vy[r], vy[r]);
#pragma unroll
            for (int w = 0; w < WAY; w++) {
                ffma2(acc[r][w], vx[r], cw[w][0]);
                ffma2(acc[r][w], vy[r], cw[w][1]);
            }
        }
        if (i < 4) {
#pragma unroll
            for (int r = 0; r < ROWS; r++) { vx[r] = nx[r]; vy[r] = ny[r]; }
        }
    }

#pragma unroll
    for (int r = 0; r < ROWS; r++) {
        float s[6];
#pragma unroll
        for (int k = 0; k < 6; k++) {
            float2 f = upk(acc[r][k]);
            s[k] = f.x + f.y;
        }
#pragma unroll
        for (int o = 16; o; o >>= 1) {
#pragma unroll
            for (int k = 0; k < 6; k++) s[k] += __shfl_xor_sync(0xffffffffu, s[k], o);
        }
        float inv = 1.0f / fmaxf(sqrtf(s[5]), EPS);
        if (lane < WAY) {
            float a = (lane == 0) ? s[0] :
                      (lane == 1) ? s[1] :
                      (lane == 2) ? s[2] :
                      (lane == 3) ? s[3] : s[4];
            g_sim[lane][SHOT + row0 + r] = a * inv;
        }
    }
}

// ---------------- kernel 3: top-8 per way + prototype build ----------------
#define K3_THREADS 512
__device__ __forceinline__ void merge8(float* av, int* ai,
                                       const float* bv, const int* bi) {
    float tv[TOPK]; int ti[TOPK];
    int ia = 0, ib = 0;
#pragma unroll
    for (int k = 0; k < TOPK; k++) {
        float va = av[ia], vb = bv[ib];
        bool takeA = (va > vb) || (va == vb && ai[ia] <= bi[ib]);
        if (takeA) { tv[k] = va; ti[k] = ai[ia]; ia++; }
        else       { tv[k] = vb; ti[k] = bi[ib]; ib++; }
    }
#pragma unroll
    for (int k = 0; k < TOPK; k++) { av[k] = tv[k]; ai[k] = ti[k]; }
}

__global__ void k3_topk_proto(const float* __restrict__ inst,
                              const float* __restrict__ mem) {
    int w = blockIdx.x;
    int tid = threadIdx.x;
    const float* sim = g_sim[w];

    float bv[TOPK]; int bi[TOPK];
#pragma unroll
    for (int j = 0; j < TOPK; j++) { bv[j] = -FLT_MAX; bi[j] = 0x7fffffff; }

    for (int i = tid; i < NSIM; i += K3_THREADS) {
        float v = sim[i];
        if (v > bv[TOPK - 1]) {
            int j = TOPK - 1;
            while (j > 0 && v > bv[j - 1]) { bv[j] = bv[j - 1]; bi[j] = bi[j - 1]; j--; }
            bv[j] = v; bi[j] = i;
        }
    }

    __shared__ float shv[K3_THREADS][TOPK];
    __shared__ int   shi[K3_THREADS][TOPK];
#pragma unroll
    for (int j = 0; j < TOPK; j++) { shv[tid][j] = bv[j]; shi[tid][j] = bi[j]; }
    __syncthreads();

    for (int s = K3_THREADS / 2; s >= 1; s >>= 1) {
        if (tid < s)
            merge8(shv[tid], shi[tid], shv[tid + s], shi[tid + s]);
        __syncthreads();
    }

    // ---- fused prototype build (replaces old k4) ----
    __shared__ float svals[TOPK];
    __shared__ int   sidx[TOPK];
    __shared__ float red[32];
    if (tid < TOPK) { svals[tid] = shv[0][tid]; sidx[tid] = shi[0][tid]; }
    __syncthreads();

    float denom = 0.f;
#pragma unroll
    for (int j = 0; j < TOPK; j++) denom += svals[j];

    float pd[2] = {0.f, 0.f};
    float ssacc = 0.f;
#pragma unroll
    for (int t = 0; t < 2; t++) {
        int d = tid + t * K3_THREADS;
        if (d < EMB) {
            float numer = 0.f;
#pragma unroll
            for (int j = 0; j < TOPK; j++) {
                int idx = sidx[j];
                const float* src = (idx < SHOT)
                    ? inst + (size_t)(idx * WAY + w) * EMB
                    : mem + (size_t)(idx - SHOT) * EMB;
                numer += svals[j] * src[d];
            }
            float p = numer / denom;
            pd[t] = p;
            ssacc += p * p;
        }
    }

    int lane = tid & 31, wid = tid >> 5;
    float ss = ssacc;
#pragma unroll
    for (int o = 16; o; o >>= 1) ss += __shfl_xor_sync(0xffffffffu, ss, o);
    if (lane == 0) red[wid] = ss;
    __syncthreads();
    if (wid == 0) {
        float tt = (lane < (K3_THREADS >> 5)) ? red[lane] : 0.f;
#pragma unroll
        for (int o = 16; o; o >>= 1) tt += __shfl_xor_sync(0xffffffffu, tt, o);
        if (lane == 0) red[0] = 1.0f / fmaxf(sqrtf(tt), EPS);
    }
    __syncthreads();
    float inv = red[0];
#pragma unroll
    for (int t = 0; t < 2; t++) {
        int d = tid + t * K3_THREADS;
        if (d < EMB) g_proto[w][d] = pd[t] * inv;
    }
}

// ---------------- kernel 5: logits ----------------------------------------
__global__ void k5_logits(const float* __restrict__ inst, float* __restrict__ out) {
    int q = blockIdx.x;
    int w = threadIdx.x >> 5;
    int lane = threadIdx.x & 31;
    const float* qr = inst + (size_t)(SHOT * WAY + q) * EMB;

    float dot = 0.f;
#pragma unroll
    for (int i = 0; i < 20; i++) {
        int d = lane + 32 * i;
        dot += qr[d] * g_proto[w][d];
    }
#pragma unroll
    for (int o = 16; o; o >>= 1) dot += __shfl_xor_sync(0xffffffffu, dot, o);
    if (lane == 0) out[q * WAY + w] = dot * INV_TEMP;
}

// ---------------- launch ----------------------------------------------------
extern "C" void kernel_launch(void* const* d_in, const int* in_sizes, int n_in,
                              void* d_out, int out_size) {
    const float* inst = (const float*)d_in[0];   // [100, 640] fp32
    const float* mem  = (const float*)d_in[1];   // [100000, 640] fp32
    float* out = (float*)d_out;                  // [75, 5] fp32

    k1_support<<<1, 800>>>(inst);

    int warps  = (NMEM + ROWS - 1) / ROWS;       // 25000
    int blocks = (warps + 7) / 8;                // 3125
    k2_memscan<<<blocks, 256>>>(mem);

    k3_topk_proto<<<WAY, K3_THREADS>>>(inst, mem);
    k5_logits<<<QUERY * WAY, WAY * 32>>>(inst, out);
}

// round 4
// speedup vs baseline: 1.3498x; 1.1401x over previous
#include <cuda_runtime.h>
#include <cuda_bf16.h>
#include <math.h>
#include <float.h>

#define WAY 5
#define SHOT 5
#define QUERY 15
#define EMB 640
#define NMEM 100000
#define NSIM (SHOT + NMEM)   // 100005 candidates per way
#define TOPK 8
#define EPS 1e-12f
#define INV_TEMP (1.0f / 64.0f)

#define ROWS 4               // rows per warp in k2
#define SPLITS 8             // scan splits per way in k3a
#define CHUNK ((NSIM + SPLITS - 1) / SPLITS)   // 12501

// ---------------- device scratch (static, allocation-free) ----------------
__device__ float g_c[WAY][EMB];           // per-way centroid of normalized supports
__device__ float g_supn[SHOT * WAY][EMB]; // normalized support rows
__device__ float g_sim[WAY][NSIM];        // similarity vector per way
__device__ float g_pv[WAY][SPLITS][TOPK]; // partial top-k values
__device__ int   g_pi[WAY][SPLITS][TOPK]; // partial top-k indices

// ---------------- kernel 1: supports -> sup_n, centroids, sim_sup ----------
__global__ void k1_support(const float* __restrict__ inst) {
    int wid  = threadIdx.x >> 5;
    int lane = threadIdx.x & 31;

    if (wid < SHOT * WAY) {
        const float* row = inst + wid * EMB;
        float v[20];
        float ss = 0.f;
#pragma unroll
        for (int i = 0; i < 20; i++) {
            v[i] = row[lane + 32 * i];
            ss += v[i] * v[i];
        }
#pragma unroll
        for (int o = 16; o; o >>= 1) ss += __shfl_xor_sync(0xffffffffu, ss, o);
        float inv = 1.0f / fmaxf(sqrtf(ss), EPS);
#pragma unroll
        for (int i = 0; i < 20; i++) g_supn[wid][lane + 32 * i] = v[i] * inv;
    }
    __syncthreads();

    for (int idx = threadIdx.x; idx < WAY * EMB; idx += blockDim.x) {
        int w = idx / EMB, d = idx % EMB;
        float s = 0.f;
#pragma unroll
        for (int t = 0; t < SHOT; t++) s += g_supn[t * WAY + w][d];
        g_c[w][d] = s * (1.0f / SHOT);
    }
    __syncthreads();

    if (wid < WAY * SHOT) {
        int w = wid / SHOT, t = wid % SHOT;
        float dot = 0.f;
        for (int i = lane; i < EMB; i += 32)
            dot += g_c[w][i] * g_supn[t * WAY + w][i];
#pragma unroll
        for (int o = 16; o; o >>= 1) dot += __shfl_xor_sync(0xffffffffu, dot, o);
        if (lane == 0) g_sim[w][t] = dot;
    }
}

// ---------------- kernel 2: memory-bank scan (DRAM-bound target) -----------
// Lean register budget (~72 regs): scalar f32 accumulators, 4 rows/warp,
// 4 batched LDG.128 per iteration; 16 warps/SM guaranteed (no spill risk).
__global__ void __launch_bounds__(256, 2) k2_memscan(const float* __restrict__ mem) {
    __shared__ float4 sc[WAY][EMB / 4];   // centroids, 12.8 KB
    for (int i = threadIdx.x; i < WAY * EMB / 4; i += blockDim.x)
        (&sc[0][0])[i] = ((const float4*)g_c)[i];
    __syncthreads();

    int wg   = (blockIdx.x * blockDim.x + threadIdx.x) >> 5;
    int lane = threadIdx.x & 31;
    int row0 = wg * ROWS;
    if (row0 >= NMEM) return;

    const float4* base = (const float4*)(mem + (size_t)row0 * EMB);  // row stride 160

    float acc[ROWS][6];
#pragma unroll
    for (int r = 0; r < ROWS; r++)
#pragma unroll
        for (int k = 0; k < 6; k++) acc[r][k] = 0.f;

#pragma unroll
    for (int i = 0; i < 5; i++) {
        int ci = lane + 32 * i;
        // batched independent loads (MLP >= 4 per warp)
        float4 v[ROWS];
#pragma unroll
        for (int r = 0; r < ROWS; r++) v[r] = __ldg(base + (size_t)r * 160 + ci);

        float4 c0 = sc[0][ci], c1 = sc[1][ci], c2 = sc[2][ci],
               c3 = sc[3][ci], c4 = sc[4][ci];
#pragma unroll
        for (int r = 0; r < ROWS; r++) {
            float4 x = v[r];
            acc[r][5] += x.x * x.x  + x.y * x.y  + x.z * x.z  + x.w * x.w;
            acc[r][0] += x.x * c0.x + x.y * c0.y + x.z * c0.z + x.w * c0.w;
            acc[r][1] += x.x * c1.x + x.y * c1.y + x.z * c1.z + x.w * c1.w;
            acc[r][2] += x.x * c2.x + x.y * c2.y + x.z * c2.z + x.w * c2.w;
            acc[r][3] += x.x * c3.x + x.y * c3.y + x.z * c3.z + x.w * c3.w;
            acc[r][4] += x.x * c4.x + x.y * c4.y + x.z * c4.z + x.w * c4.w;
        }
    }

#pragma unroll
    for (int r = 0; r < ROWS; r++) {
#pragma unroll
        for (int o = 16; o; o >>= 1) {
#pragma unroll
            for (int k = 0; k < 6; k++)
                acc[r][k] += __shfl_xor_sync(0xffffffffu, acc[r][k], o);
        }
        float inv = 1.0f / fmaxf(sqrtf(acc[r][5]), EPS);
        if (lane < WAY) {
            float a = (lane == 0) ? acc[r][0] :
                      (lane == 1) ? acc[r][1] :
                      (lane == 2) ? acc[r][2] :
                      (lane == 3) ? acc[r][3] : acc[r][4];
            g_sim[lane][SHOT + row0 + r] = a * inv;
        }
    }
}

// ---------------- top-k helpers ---------------------------------------------
__device__ __forceinline__ void merge8(float* av, int* ai,
                                       const float* bv, const int* bi) {
    float tv[TOPK]; int ti[TOPK];
    int ia = 0, ib = 0;
#pragma unroll
    for (int k = 0; k < TOPK; k++) {
        float va = av[ia], vb = bv[ib];
        bool takeA = (va > vb) || (va == vb && ai[ia] <= bi[ib]);
        if (takeA) { tv[k] = va; ti[k] = ai[ia]; ia++; }
        else       { tv[k] = vb; ti[k] = bi[ib]; ib++; }
    }
#pragma unroll
    for (int k = 0; k < TOPK; k++) { av[k] = tv[k]; ai[k] = ti[k]; }
}

__device__ __forceinline__ void insert8(float* bv, int* bi, float v, int i) {
    if (v > bv[TOPK - 1]) {
        int j = TOPK - 1;
        while (j > 0 && v > bv[j - 1]) { bv[j] = bv[j - 1]; bi[j] = bi[j - 1]; j--; }
        bv[j] = v; bi[j] = i;
    }
}

// ---------------- kernel 3a: partial top-8 (40 blocks, batched loads) ------
#define K3A_THREADS 256
__global__ void k3a_topk() {
    int w = blockIdx.x / SPLITS;
    int s = blockIdx.x % SPLITS;
    int lo = s * CHUNK;
    int hi = min(lo + CHUNK, NSIM);
    const float* sim = g_sim[w];
    int tid = threadIdx.x;

    float bv[TOPK]; int bi[TOPK];
#pragma unroll
    for (int j = 0; j < TOPK; j++) { bv[j] = -FLT_MAX; bi[j] = 0x7fffffff; }

    // batched: 4 independent loads before the branchy inserts (MLP >= 4)
    int i = lo + tid;
    for (; i + 3 * K3A_THREADS < hi; i += 4 * K3A_THREADS) {
        float v0 = sim[i];
        float v1 = sim[i + K3A_THREADS];
        float v2 = sim[i + 2 * K3A_THREADS];
        float v3 = sim[i + 3 * K3A_THREADS];
        insert8(bv, bi, v0, i);
        insert8(bv, bi, v1, i + K3A_THREADS);
        insert8(bv, bi, v2, i + 2 * K3A_THREADS);
        insert8(bv, bi, v3, i + 3 * K3A_THREADS);
    }
    for (; i < hi; i += K3A_THREADS) insert8(bv, bi, sim[i], i);

    __shared__ float shv[K3A_THREADS][TOPK];
    __shared__ int   shi[K3A_THREADS][TOPK];
#pragma unroll
    for (int j = 0; j < TOPK; j++) { shv[tid][j] = bv[j]; shi[tid][j] = bi[j]; }
    __syncthreads();

    for (int step = K3A_THREADS / 2; step >= 1; step >>= 1) {
        if (tid < step)
            merge8(shv[tid], shi[tid], shv[tid + step], shi[tid + step]);
        __syncthreads();
    }
    if (tid < TOPK) {
        g_pv[w][s][tid] = shv[0][tid];
        g_pi[w][s][tid] = shi[0][tid];
    }
}

// ---------------- kernel 3b: merge + prototype + logits column -------------
// one block per way, 640 threads
__global__ void k3b_proto_logits(const float* __restrict__ inst,
                                 const float* __restrict__ mem,
                                 float* __restrict__ out) {
    int w = blockIdx.x;
    int tid = threadIdx.x;

    __shared__ float svals[TOPK];
    __shared__ int   sidx[TOPK];
    __shared__ float red[32];
    __shared__ float sp[EMB];

    // thread 0 merges 64 candidates sequentially (tiny)
    if (tid == 0) {
        float bv[TOPK]; int bi[TOPK];
#pragma unroll
        for (int j = 0; j < TOPK; j++) { bv[j] = -FLT_MAX; bi[j] = 0x7fffffff; }
        for (int s = 0; s < SPLITS; s++) {
#pragma unroll
            for (int j = 0; j < TOPK; j++) {
                float v = g_pv[w][s][j];
                int   ix = g_pi[w][s][j];
                if (v > bv[TOPK - 1] ||
                    (v == bv[TOPK - 1] && ix < bi[TOPK - 1])) {
                    int p = TOPK - 1;
                    while (p > 0 && (v > bv[p - 1] ||
                                     (v == bv[p - 1] && ix < bi[p - 1]))) {
                        bv[p] = bv[p - 1]; bi[p] = bi[p - 1]; p--;
                    }
                    bv[p] = v; bi[p] = ix;
                }
            }
        }
#pragma unroll
        for (int j = 0; j < TOPK; j++) { svals[j] = bv[j]; sidx[j] = bi[j]; }
    }
    __syncthreads();

    // prototype dim per thread
    float denom = 0.f;
#pragma unroll
    for (int j = 0; j < TOPK; j++) denom += svals[j];

    float numer = 0.f;
#pragma unroll
    for (int j = 0; j < TOPK; j++) {
        int idx = sidx[j];
        const float* src = (idx < SHOT)
            ? inst + (size_t)(idx * WAY + w) * EMB
            : mem + (size_t)(idx - SHOT) * EMB;
        numer += svals[j] * src[tid];
    }
    float p = numer / denom;

    // block reduce sum of squares (20 warps)
    float ss = p * p;
    int lane = tid & 31, wid = tid >> 5;
#pragma unroll
    for (int o = 16; o; o >>= 1) ss += __shfl_xor_sync(0xffffffffu, ss, o);
    if (lane == 0) red[wid] = ss;
    __syncthreads();
    if (wid == 0) {
        float t = (lane < 20) ? red[lane] : 0.f;
#pragma unroll
        for (int o = 16; o; o >>= 1) t += __shfl_xor_sync(0xffffffffu, t, o);
        if (lane == 0) red[0] = 1.0f / fmaxf(sqrtf(t), EPS);
    }
    __syncthreads();
    sp[tid] = p * red[0];
    __syncthreads();

    // logits column: 20 warps, warp u handles queries u, u+20, u+40, u+60
    for (int q = wid; q < QUERY * WAY; q += 20) {
        const float* qr = inst + (size_t)(SHOT * WAY + q) * EMB;
        float dot = 0.f;
#pragma unroll
        for (int i = 0; i < 20; i++) {
            int d = lane + 32 * i;
            dot += qr[d] * sp[d];
        }
#pragma unroll
        for (int o = 16; o; o >>= 1) dot += __shfl_xor_sync(0xffffffffu, dot, o);
        if (lane == 0) out[q * WAY + w] = dot * INV_TEMP;
    }
}

// ---------------- launch ----------------------------------------------------
extern "C" void kernel_launch(void* const* d_in, const int* in_sizes, int n_in,
                              void* d_out, int out_size) {
    const float* inst = (const float*)d_in[0];   // [100, 640] fp32
    const float* mem  = (const float*)d_in[1];   // [100000, 640] fp32
    float* out = (float*)d_out;                  // [75, 5] fp32

    k1_support<<<1, 800>>>(inst);

    int warps  = (NMEM + ROWS - 1) / ROWS;       // 25000
    int blocks = (warps + 7) / 8;                // 3125
    k2_memscan<<<blocks, 256>>>(mem);

    k3a_topk<<<WAY * SPLITS, K3A_THREADS>>>();
    k3b_proto_logits<<<WAY, EMB>>>(inst, mem, out);
}

// round 5
// speedup vs baseline: 1.8162x; 1.3455x over previous
#include <cuda_runtime.h>
#include <cuda_bf16.h>
#include <math.h>
#include <float.h>

#define WAY 5
#define SHOT 5
#define QUERY 15
#define EMB 640
#define NMEM 100000
#define NSIM (SHOT + NMEM)   // 100005 candidates per way
#define TOPK 8
#define EPS 1e-12f
#define INV_TEMP (1.0f / 64.0f)

#define ROWS 4               // rows per warp in k2
#define SPLITS 8             // scan splits per way in k3a
#define CHUNK ((NSIM + SPLITS - 1) / SPLITS)   // 12501

// ---------------- device scratch (static, allocation-free) ----------------
__device__ float g_c[WAY][EMB];           // per-way centroid of normalized supports
__device__ float g_supn[SHOT * WAY][EMB]; // normalized support rows
__device__ float g_sim[WAY][NSIM];        // similarity vector per way
__device__ float g_pv[WAY][SPLITS][TOPK]; // partial top-k values
__device__ int   g_pi[WAY][SPLITS][TOPK]; // partial top-k indices

// ---------------- kernel 1: supports -> sup_n, centroids, sim_sup ----------
__global__ void k1_support(const float* __restrict__ inst) {
    int wid  = threadIdx.x >> 5;
    int lane = threadIdx.x & 31;

    if (wid < SHOT * WAY) {
        const float* row = inst + wid * EMB;
        float v[20];
        float ss = 0.f;
#pragma unroll
        for (int i = 0; i < 20; i++) {
            v[i] = row[lane + 32 * i];
            ss += v[i] * v[i];
        }
#pragma unroll
        for (int o = 16; o; o >>= 1) ss += __shfl_xor_sync(0xffffffffu, ss, o);
        float inv = 1.0f / fmaxf(sqrtf(ss), EPS);
#pragma unroll
        for (int i = 0; i < 20; i++) g_supn[wid][lane + 32 * i] = v[i] * inv;
    }
    __syncthreads();

    for (int idx = threadIdx.x; idx < WAY * EMB; idx += blockDim.x) {
        int w = idx / EMB, d = idx % EMB;
        float s = 0.f;
#pragma unroll
        for (int t = 0; t < SHOT; t++) s += g_supn[t * WAY + w][d];
        g_c[w][d] = s * (1.0f / SHOT);
    }
    __syncthreads();

    if (wid < WAY * SHOT) {
        int w = wid / SHOT, t = wid % SHOT;
        float dot = 0.f;
        for (int i = lane; i < EMB; i += 32)
            dot += g_c[w][i] * g_supn[t * WAY + w][i];
#pragma unroll
        for (int o = 16; o; o >>= 1) dot += __shfl_xor_sync(0xffffffffu, dot, o);
        if (lane == 0) g_sim[w][t] = dot;
    }
}

// ---------------- kernel 2: memory-bank scan (DRAM-bound target) -----------
// 4 rows/warp, double-chunk prefetch => 8 LDG.128 in flight per warp (MLP~8).
// ~90 regs, fits 2 blocks/SM under __launch_bounds__(256,2) with no spills.
__global__ void __launch_bounds__(256, 2) k2_memscan(const float* __restrict__ mem) {
    __shared__ float4 sc[WAY][EMB / 4];   // centroids, 12.8 KB
    for (int i = threadIdx.x; i < WAY * EMB / 4; i += blockDim.x)
        (&sc[0][0])[i] = ((const float4*)g_c)[i];
    __syncthreads();

    int wg   = (blockIdx.x * blockDim.x + threadIdx.x) >> 5;
    int lane = threadIdx.x & 31;
    int row0 = wg * ROWS;
    if (row0 >= NMEM) return;

    const float4* base = (const float4*)(mem + (size_t)row0 * EMB);  // row stride 160

    float acc[ROWS][6];
#pragma unroll
    for (int r = 0; r < ROWS; r++)
#pragma unroll
        for (int k = 0; k < 6; k++) acc[r][k] = 0.f;

    // prefetch chunk 0
    float4 v[ROWS];
#pragma unroll
    for (int r = 0; r < ROWS; r++) v[r] = __ldg(base + (size_t)r * 160 + lane);

#pragma unroll
    for (int i = 0; i < 5; i++) {
        int ci = lane + 32 * i;

        // prefetch chunk i+1 before computing chunk i (keeps 8 LDGs in flight)
        float4 nx[ROWS];
        if (i < 4) {
#pragma unroll
            for (int r = 0; r < ROWS; r++)
                nx[r] = __ldg(base + (size_t)r * 160 + ci + 32);
        }

        float4 c0 = sc[0][ci], c1 = sc[1][ci], c2 = sc[2][ci],
               c3 = sc[3][ci], c4 = sc[4][ci];
#pragma unroll
        for (int r = 0; r < ROWS; r++) {
            float4 x = v[r];
            acc[r][5] += x.x * x.x  + x.y * x.y  + x.z * x.z  + x.w * x.w;
            acc[r][0] += x.x * c0.x + x.y * c0.y + x.z * c0.z + x.w * c0.w;
            acc[r][1] += x.x * c1.x + x.y * c1.y + x.z * c1.z + x.w * c1.w;
            acc[r][2] += x.x * c2.x + x.y * c2.y + x.z * c2.z + x.w * c2.w;
            acc[r][3] += x.x * c3.x + x.y * c3.y + x.z * c3.z + x.w * c3.w;
            acc[r][4] += x.x * c4.x + x.y * c4.y + x.z * c4.z + x.w * c4.w;
        }
        if (i < 4) {
#pragma unroll
            for (int r = 0; r < ROWS; r++) v[r] = nx[r];
        }
    }

#pragma unroll
    for (int r = 0; r < ROWS; r++) {
#pragma unroll
        for (int o = 16; o; o >>= 1) {
#pragma unroll
            for (int k = 0; k < 6; k++)
                acc[r][k] += __shfl_xor_sync(0xffffffffu, acc[r][k], o);
        }
        float inv = 1.0f / fmaxf(sqrtf(acc[r][5]), EPS);
        if (lane < WAY) {
            float a = (lane == 0) ? acc[r][0] :
                      (lane == 1) ? acc[r][1] :
                      (lane == 2) ? acc[r][2] :
                      (lane == 3) ? acc[r][3] : acc[r][4];
            g_sim[lane][SHOT + row0 + r] = a * inv;
        }
    }
}

// ---------------- top-k helpers ---------------------------------------------
__device__ __forceinline__ void merge8(float* av, int* ai,
                                       const float* bv, const int* bi) {
    float tv[TOPK]; int ti[TOPK];
    int ia = 0, ib = 0;
#pragma unroll
    for (int k = 0; k < TOPK; k++) {
        float va = av[ia], vb = bv[ib];
        bool takeA = (va > vb) || (va == vb && ai[ia] <= bi[ib]);
        if (takeA) { tv[k] = va; ti[k] = ai[ia]; ia++; }
        else       { tv[k] = vb; ti[k] = bi[ib]; ib++; }
    }
#pragma unroll
    for (int k = 0; k < TOPK; k++) { av[k] = tv[k]; ai[k] = ti[k]; }
}

__device__ __forceinline__ void insert8(float* bv, int* bi, float v, int i) {
    if (v > bv[TOPK - 1]) {
        int j = TOPK - 1;
        while (j > 0 && v > bv[j - 1]) { bv[j] = bv[j - 1]; bi[j] = bi[j - 1]; j--; }
        bv[j] = v; bi[j] = i;
    }
}

// ---------------- kernel 3a: partial top-8 (40 blocks, batched loads) ------
#define K3A_THREADS 256
__global__ void k3a_topk() {
    int w = blockIdx.x / SPLITS;
    int s = blockIdx.x % SPLITS;
    int lo = s * CHUNK;
    int hi = min(lo + CHUNK, NSIM);
    const float* sim = g_sim[w];
    int tid = threadIdx.x;

    float bv[TOPK]; int bi[TOPK];
#pragma unroll
    for (int j = 0; j < TOPK; j++) { bv[j] = -FLT_MAX; bi[j] = 0x7fffffff; }

    int i = lo + tid;
    for (; i + 3 * K3A_THREADS < hi; i += 4 * K3A_THREADS) {
        float v0 = sim[i];
        float v1 = sim[i + K3A_THREADS];
        float v2 = sim[i + 2 * K3A_THREADS];
        float v3 = sim[i + 3 * K3A_THREADS];
        insert8(bv, bi, v0, i);
        insert8(bv, bi, v1, i + K3A_THREADS);
        insert8(bv, bi, v2, i + 2 * K3A_THREADS);
        insert8(bv, bi, v3, i + 3 * K3A_THREADS);
    }
    for (; i < hi; i += K3A_THREADS) insert8(bv, bi, sim[i], i);

    __shared__ float shv[K3A_THREADS][TOPK];
    __shared__ int   shi[K3A_THREADS][TOPK];
#pragma unroll
    for (int j = 0; j < TOPK; j++) { shv[tid][j] = bv[j]; shi[tid][j] = bi[j]; }
    __syncthreads();

    for (int step = K3A_THREADS / 2; step >= 1; step >>= 1) {
        if (tid < step)
            merge8(shv[tid], shi[tid], shv[tid + step], shi[tid + step]);
        __syncthreads();
    }
    if (tid < TOPK) {
        g_pv[w][s][tid] = shv[0][tid];
        g_pi[w][s][tid] = shi[0][tid];
    }
}

// ---------------- kernel 3b: merge + prototype + logits column -------------
// one block per way, 640 threads. Partial candidates are staged into shared
// memory IN PARALLEL (64 global loads by 64 threads) before the serial merge,
// so the merge runs at LDS latency instead of DRAM latency.
__global__ void k3b_proto_logits(const float* __restrict__ inst,
                                 const float* __restrict__ mem,
                                 float* __restrict__ out) {
    int w = blockIdx.x;
    int tid = threadIdx.x;

    __shared__ float cv[SPLITS * TOPK];
    __shared__ int   cix[SPLITS * TOPK];
    __shared__ float svals[TOPK];
    __shared__ int   sidx[TOPK];
    __shared__ float red[32];
    __shared__ float sp[EMB];

    // parallel staging of all 64 partial candidates
    if (tid < SPLITS * TOPK) {
        cv[tid]  = (&g_pv[w][0][0])[tid];
        cix[tid] = (&g_pi[w][0][0])[tid];
    }
    __syncthreads();

    // thread 0 merges 64 candidates from shared (fast)
    if (tid == 0) {
        float bv[TOPK]; int bi[TOPK];
#pragma unroll
        for (int j = 0; j < TOPK; j++) { bv[j] = -FLT_MAX; bi[j] = 0x7fffffff; }
        for (int c = 0; c < SPLITS * TOPK; c++) {
            float v = cv[c];
            int   ix = cix[c];
            if (v > bv[TOPK - 1] ||
                (v == bv[TOPK - 1] && ix < bi[TOPK - 1])) {
                int p = TOPK - 1;
                while (p > 0 && (v > bv[p - 1] ||
                                 (v == bv[p - 1] && ix < bi[p - 1]))) {
                    bv[p] = bv[p - 1]; bi[p] = bi[p - 1]; p--;
                }
                bv[p] = v; bi[p] = ix;
            }
        }
#pragma unroll
        for (int j = 0; j < TOPK; j++) { svals[j] = bv[j]; sidx[j] = bi[j]; }
    }
    __syncthreads();

    // prototype dim per thread
    float denom = 0.f;
#pragma unroll
    for (int j = 0; j < TOPK; j++) denom += svals[j];

    float numer = 0.f;
#pragma unroll
    for (int j = 0; j < TOPK; j++) {
        int idx = sidx[j];
        const float* src = (idx < SHOT)
            ? inst + (size_t)(idx * WAY + w) * EMB
            : mem + (size_t)(idx - SHOT) * EMB;
        numer += svals[j] * src[tid];
    }
    float p = numer / denom;

    // block reduce sum of squares (20 warps)
    float ss = p * p;
    int lane = tid & 31, wid = tid >> 5;
#pragma unroll
    for (int o = 16; o; o >>= 1) ss += __shfl_xor_sync(0xffffffffu, ss, o);
    if (lane == 0) red[wid] = ss;
    __syncthreads();
    if (wid == 0) {
        float t = (lane < 20) ? red[lane] : 0.f;
#pragma unroll
        for (int o = 16; o; o >>= 1) t += __shfl_xor_sync(0xffffffffu, t, o);
        if (lane == 0) red[0] = 1.0f / fmaxf(sqrtf(t), EPS);
    }
    __syncthreads();
    sp[tid] = p * red[0];
    __syncthreads();

    // logits column: 20 warps, warp u handles queries u, u+20, u+40, u+60
    for (int q = wid; q < QUERY * WAY; q += 20) {
        const float* qr = inst + (size_t)(SHOT * WAY + q) * EMB;
        float dot = 0.f;
#pragma unroll
        for (int i = 0; i < 20; i++) {
            int d = lane + 32 * i;
            dot += qr[d] * sp[d];
        }
#pragma unroll
        for (int o = 16; o; o >>= 1) dot += __shfl_xor_sync(0xffffffffu, dot, o);
        if (lane == 0) out[q * WAY + w] = dot * INV_TEMP;
    }
}

// ---------------- launch ----------------------------------------------------
extern "C" void kernel_launch(void* const* d_in, const int* in_sizes, int n_in,
                              void* d_out, int out_size) {
    const float* inst = (const float*)d_in[0];   // [100, 640] fp32
    const float* mem  = (const float*)d_in[1];   // [100000, 640] fp32
    float* out = (float*)d_out;                  // [75, 5] fp32

    k1_support<<<1, 800>>>(inst);

    int warps  = (NMEM + ROWS - 1) / ROWS;       // 25000
    int blocks = (warps + 7) / 8;                // 3125
    k2_memscan<<<blocks, 256>>>(mem);

    k3a_topk<<<WAY * SPLITS, K3A_THREADS>>>();
    k3b_proto_logits<<<WAY, EMB>>>(inst, mem, out);
}

// round 6
// speedup vs baseline: 1.8428x; 1.0146x over previous
#include <cuda_runtime.h>
#include <cuda_bf16.h>
#include <math.h>
#include <float.h>

#define WAY 5
#define SHOT 5
#define QUERY 15
#define EMB 640
#define NMEM 100000
#define NSIM (SHOT + NMEM)   // 100005 candidates per way
#define TOPK 8
#define EPS 1e-12f
#define INV_TEMP (1.0f / 64.0f)

#define ROWS 4               // rows per warp in k2
#define SPLITS 8             // scan splits per way in k3a
#define CHUNK ((NSIM + SPLITS - 1) / SPLITS)   // 12501

// ---------------- device scratch (static, allocation-free) ----------------
__device__ float g_c[WAY][EMB];           // per-way centroid of normalized supports
__device__ float g_supn[SHOT * WAY][EMB]; // normalized support rows
__device__ float g_sim[WAY][NSIM];        // similarity vector per way
__device__ float g_pv[WAY][SPLITS][TOPK]; // partial top-k values
__device__ int   g_pi[WAY][SPLITS][TOPK]; // partial top-k indices

// ---------------- kernel 1: supports -> sup_n, centroids, sim_sup ----------
__global__ void k1_support(const float* __restrict__ inst) {
    int wid  = threadIdx.x >> 5;
    int lane = threadIdx.x & 31;

    if (wid < SHOT * WAY) {
        const float* row = inst + wid * EMB;
        float v[20];
        float ss = 0.f;
#pragma unroll
        for (int i = 0; i < 20; i++) {
            v[i] = row[lane + 32 * i];
            ss += v[i] * v[i];
        }
#pragma unroll
        for (int o = 16; o; o >>= 1) ss += __shfl_xor_sync(0xffffffffu, ss, o);
        float inv = 1.0f / fmaxf(sqrtf(ss), EPS);
#pragma unroll
        for (int i = 0; i < 20; i++) g_supn[wid][lane + 32 * i] = v[i] * inv;
    }
    __syncthreads();

    for (int idx = threadIdx.x; idx < WAY * EMB; idx += blockDim.x) {
        int w = idx / EMB, d = idx % EMB;
        float s = 0.f;
#pragma unroll
        for (int t = 0; t < SHOT; t++) s += g_supn[t * WAY + w][d];
        g_c[w][d] = s * (1.0f / SHOT);
    }
    __syncthreads();

    if (wid < WAY * SHOT) {
        int w = wid / SHOT, t = wid % SHOT;
        float dot = 0.f;
        for (int i = lane; i < EMB; i += 32)
            dot += g_c[w][i] * g_supn[t * WAY + w][i];
#pragma unroll
        for (int o = 16; o; o >>= 1) dot += __shfl_xor_sync(0xffffffffu, dot, o);
        if (lane == 0) g_sim[w][t] = dot;
    }
}

// ---------------- kernel 2: memory-bank scan (DRAM-bound target) -----------
// 4 rows/warp, double-chunk prefetch => 8 LDG.128 in flight per warp (MLP~8).
// ~90 regs, fits 2 blocks/SM under __launch_bounds__(256,2) with no spills.
__global__ void __launch_bounds__(256, 2) k2_memscan(const float* __restrict__ mem) {
    __shared__ float4 sc[WAY][EMB / 4];   // centroids, 12.8 KB
    for (int i = threadIdx.x; i < WAY * EMB / 4; i += blockDim.x)
        (&sc[0][0])[i] = ((const float4*)g_c)[i];
    __syncthreads();

    int wg   = (blockIdx.x * blockDim.x + threadIdx.x) >> 5;
    int lane = threadIdx.x & 31;
    int row0 = wg * ROWS;
    if (row0 >= NMEM) return;

    const float4* base = (const float4*)(mem + (size_t)row0 * EMB);  // row stride 160

    float acc[ROWS][6];
#pragma unroll
    for (int r = 0; r < ROWS; r++)
#pragma unroll
        for (int k = 0; k < 6; k++) acc[r][k] = 0.f;

    // prefetch chunk 0
    float4 v[ROWS];
#pragma unroll
    for (int r = 0; r < ROWS; r++) v[r] = __ldg(base + (size_t)r * 160 + lane);

#pragma unroll
    for (int i = 0; i < 5; i++) {
        int ci = lane + 32 * i;

        // prefetch chunk i+1 before computing chunk i (keeps 8 LDGs in flight)
        float4 nx[ROWS];
        if (i < 4) {
#pragma unroll
            for (int r = 0; r < ROWS; r++)
                nx[r] = __ldg(base + (size_t)r * 160 + ci + 32);
        }

        float4 c0 = sc[0][ci], c1 = sc[1][ci], c2 = sc[2][ci],
               c3 = sc[3][ci], c4 = sc[4][ci];
#pragma unroll
        for (int r = 0; r < ROWS; r++) {
            float4 x = v[r];
            acc[r][5] += x.x * x.x  + x.y * x.y  + x.z * x.z  + x.w * x.w;
            acc[r][0] += x.x * c0.x + x.y * c0.y + x.z * c0.z + x.w * c0.w;
            acc[r][1] += x.x * c1.x + x.y * c1.y + x.z * c1.z + x.w * c1.w;
            acc[r][2] += x.x * c2.x + x.y * c2.y + x.z * c2.z + x.w * c2.w;
            acc[r][3] += x.x * c3.x + x.y * c3.y + x.z * c3.z + x.w * c3.w;
            acc[r][4] += x.x * c4.x + x.y * c4.y + x.z * c4.z + x.w * c4.w;
        }
        if (i < 4) {
#pragma unroll
            for (int r = 0; r < ROWS; r++) v[r] = nx[r];
        }
    }

#pragma unroll
    for (int r = 0; r < ROWS; r++) {
#pragma unroll
        for (int o = 16; o; o >>= 1) {
#pragma unroll
            for (int k = 0; k < 6; k++)
                acc[r][k] += __shfl_xor_sync(0xffffffffu, acc[r][k], o);
        }
        float inv = 1.0f / fmaxf(sqrtf(acc[r][5]), EPS);
        if (lane < WAY) {
            float a = (lane == 0) ? acc[r][0] :
                      (lane == 1) ? acc[r][1] :
                      (lane == 2) ? acc[r][2] :
                      (lane == 3) ? acc[r][3] : acc[r][4];
            g_sim[lane][SHOT + row0 + r] = a * inv;
        }
    }
}

// ---------------- top-k helpers ---------------------------------------------
__device__ __forceinline__ void merge8(float* av, int* ai,
                                       const float* bv, const int* bi) {
    float tv[TOPK]; int ti[TOPK];
    int ia = 0, ib = 0;
#pragma unroll
    for (int k = 0; k < TOPK; k++) {
        float va = av[ia], vb = bv[ib];
        bool takeA = (va > vb) || (va == vb && ai[ia] <= bi[ib]);
        if (takeA) { tv[k] = va; ti[k] = ai[ia]; ia++; }
        else       { tv[k] = vb; ti[k] = bi[ib]; ib++; }
    }
#pragma unroll
    for (int k = 0; k < TOPK; k++) { av[k] = tv[k]; ai[k] = ti[k]; }
}

__device__ __forceinline__ void insert8(float* bv, int* bi, float v, int i) {
    if (v > bv[TOPK - 1]) {
        int j = TOPK - 1;
        while (j > 0 && v > bv[j - 1]) { bv[j] = bv[j - 1]; bi[j] = bi[j - 1]; j--; }
        bv[j] = v; bi[j] = i;
    }
}

// ---------------- kernel 3a: partial top-8 (40 blocks, batched loads) ------
#define K3A_THREADS 256
__global__ void k3a_topk() {
    int w = blockIdx.x / SPLITS;
    int s = blockIdx.x % SPLITS;
    int lo = s * CHUNK;
    int hi = min(lo + CHUNK, NSIM);
    const float* sim = g_sim[w];
    int tid = threadIdx.x;

    float bv[TOPK]; int bi[TOPK];
#pragma unroll
    for (int j = 0; j < TOPK; j++) { bv[j] = -FLT_MAX; bi[j] = 0x7fffffff; }

    int i = lo + tid;
    for (; i + 3 * K3A_THREADS < hi; i += 4 * K3A_THREADS) {
        float v0 = sim[i];
        float v1 = sim[i + K3A_THREADS];
        float v2 = sim[i + 2 * K3A_THREADS];
        float v3 = sim[i + 3 * K3A_THREADS];
        insert8(bv, bi, v0, i);
        insert8(bv, bi, v1, i + K3A_THREADS);
        insert8(bv, bi, v2, i + 2 * K3A_THREADS);
        insert8(bv, bi, v3, i + 3 * K3A_THREADS);
    }
    for (; i < hi; i += K3A_THREADS) insert8(bv, bi, sim[i], i);

    __shared__ float shv[K3A_THREADS][TOPK];
    __shared__ int   shi[K3A_THREADS][TOPK];
#pragma unroll
    for (int j = 0; j < TOPK; j++) { shv[tid][j] = bv[j]; shi[tid][j] = bi[j]; }
    __syncthreads();

    for (int step = K3A_THREADS / 2; step >= 1; step >>= 1) {
        if (tid < step)
            merge8(shv[tid], shi[tid], shv[tid + step], shi[tid + step]);
        __syncthreads();
    }
    if (tid < TOPK) {
        g_pv[w][s][tid] = shv[0][tid];
        g_pi[w][s][tid] = shi[0][tid];
    }
}

// ---------------- kernel 3b: merge + prototype + logits column -------------
// one block per way, 640 threads. Partial candidates are staged into shared
// memory IN PARALLEL (64 global loads by 64 threads) before the serial merge,
// so the merge runs at LDS latency instead of DRAM latency.
__global__ void k3b_proto_logits(const float* __restrict__ inst,
                                 const float* __restrict__ mem,
                                 float* __restrict__ out) {
    int w = blockIdx.x;
    int tid = threadIdx.x;

    __shared__ float cv[SPLITS * TOPK];
    __shared__ int   cix[SPLITS * TOPK];
    __shared__ float svals[TOPK];
    __shared__ int   sidx[TOPK];
    __shared__ float red[32];
    __shared__ float sp[EMB];

    // parallel staging of all 64 partial candidates
    if (tid < SPLITS * TOPK) {
        cv[tid]  = (&g_pv[w][0][0])[tid];
        cix[tid] = (&g_pi[w][0][0])[tid];
    }
    __syncthreads();

    // thread 0 merges 64 candidates from shared (fast)
    if (tid == 0) {
        float bv[TOPK]; int bi[TOPK];
#pragma unroll
        for (int j = 0; j < TOPK; j++) { bv[j] = -FLT_MAX; bi[j] = 0x7fffffff; }
        for (int c = 0; c < SPLITS * TOPK; c++) {
            float v = cv[c];
            int   ix = cix[c];
            if (v > bv[TOPK - 1] ||
                (v == bv[TOPK - 1] && ix < bi[TOPK - 1])) {
                int p = TOPK - 1;
                while (p > 0 && (v > bv[p - 1] ||
                                 (v == bv[p - 1] && ix < bi[p - 1]))) {
                    bv[p] = bv[p - 1]; bi[p] = bi[p - 1]; p--;
                }
                bv[p] = v; bi[p] = ix;
            }
        }
#pragma unroll
        for (int j = 0; j < TOPK; j++) { svals[j] = bv[j]; sidx[j] = bi[j]; }
    }
    __syncthreads();

    // prototype dim per thread
    float denom = 0.f;
#pragma unroll
    for (int j = 0; j < TOPK; j++) denom += svals[j];

    float numer = 0.f;
#pragma unroll
    for (int j = 0; j < TOPK; j++) {
        int idx = sidx[j];
        const float* src = (idx < SHOT)
            ? inst + (size_t)(idx * WAY + w) * EMB
            : mem + (size_t)(idx - SHOT) * EMB;
        numer += svals[j] * src[tid];
    }
    float p = numer / denom;

    // block reduce sum of squares (20 warps)
    float ss = p * p;
    int lane = tid & 31, wid = tid >> 5;
#pragma unroll
    for (int o = 16; o; o >>= 1) ss += __shfl_xor_sync(0xffffffffu, ss, o);
    if (lane == 0) red[wid] = ss;
    __syncthreads();
    if (wid == 0) {
        float t = (lane < 20) ? red[lane] : 0.f;
#pragma unroll
        for (int o = 16; o; o >>= 1) t += __shfl_xor_sync(0xffffffffu, t, o);
        if (lane == 0) red[0] = 1.0f / fmaxf(sqrtf(t), EPS);
    }
    __syncthreads();
    sp[tid] = p * red[0];
    __syncthreads();

    // logits column: 20 warps, warp u handles queries u, u+20, u+40, u+60
    for (int q = wid; q < QUERY * WAY; q += 20) {
        const float* qr = inst + (size_t)(SHOT * WAY + q) * EMB;
        float dot = 0.f;
#pragma unroll
        for (int i = 0; i < 20; i++) {
            int d = lane + 32 * i;
            dot += qr[d] * sp[d];
        }
#pragma unroll
        for (int o = 16; o; o >>= 1) dot += __shfl_xor_sync(0xffffffffu, dot, o);
        if (lane == 0) out[q * WAY + w] = dot * INV_TEMP;
    }
}

// ---------------- launch ----------------------------------------------------
extern "C" void kernel_launch(void* const* d_in, const int* in_sizes, int n_in,
                              void* d_out, int out_size) {
    const float* inst = (const float*)d_in[0];   // [100, 640] fp32
    const float* mem  = (const float*)d_in[1];   // [100000, 640] fp32
    float* out = (float*)d_out;                  // [75, 5] fp32

    k1_support<<<1, 800>>>(inst);

    int warps  = (NMEM + ROWS - 1) / ROWS;       // 25000
    int blocks = (warps + 7) / 8;                // 3125
    k2_memscan<<<blocks, 256>>>(mem);

    k3a_topk<<<WAY * SPLITS, K3A_THREADS>>>();
    k3b_proto_logits<<<WAY, EMB>>>(inst, mem, out);
}